// round 16
// baseline (speedup 1.0000x reference)
#include <cuda_runtime.h>
#include <cuda_fp16.h>
#include <math.h>
#include <stdint.h>

#define B_    8
#define N_    2304
#define C_    192
#define HW_   48
#define HD_   64
#define NTOT_ 5915
#define RTOT_ (B_ * NTOT_)        // 47320

// ---------------- scratch ----------------
__device__ float  g_q[B_ * N_ * C_];
__device__ float  g_xr[RTOT_ * C_];
__device__ float  g_kv[RTOT_ * 128];
__device__ float  g_v2t[HD_ * RTOT_];        // TRANSPOSED: [d][row]
__device__ __half g_xh[B_ * N_ * C_];
__device__ __half g_xrh[RTOT_ * C_];
__device__ __half g_xcath[B_ * N_ * C_];
__device__ __half g_wth[C_ * C_ * 84];
__device__ __half g_wqh[C_ * C_];
__device__ __half g_wkvh[C_ * C_];
__device__ __half g_woh[C_ * C_];

// ---------------- helpers ----------------
__device__ __forceinline__ void mma_f16(float* d, const uint32_t* a, const uint32_t* b) {
    asm volatile(
        "mma.sync.aligned.m16n8k16.row.col.f32.f16.f16.f32 "
        "{%0,%1,%2,%3}, {%4,%5,%6,%7}, {%8,%9}, {%0,%1,%2,%3};"
        : "+f"(d[0]), "+f"(d[1]), "+f"(d[2]), "+f"(d[3])
        : "r"(a[0]), "r"(a[1]), "r"(a[2]), "r"(a[3]), "r"(b[0]), "r"(b[1]));
}
__device__ __forceinline__ void cp_async16(uint32_t dst, const void* src, uint32_t ssize) {
    asm volatile("cp.async.cg.shared.global [%0], [%1], 16, %2;"
                 :: "r"(dst), "l"(src), "r"(ssize) : "memory");
}
__device__ __forceinline__ void cp_commit() {
    asm volatile("cp.async.commit_group;" ::: "memory");
}
__device__ __forceinline__ void cp_wait1() {
    asm volatile("cp.async.wait_group 1;" ::: "memory");
}
__device__ __forceinline__ void cp_wait0() {
    asm volatile("cp.async.wait_group 0;" ::: "memory");
}
__device__ __forceinline__ uint32_t packh2(float a, float b) {
    __half2 h = __floats2half2_rn(a, b);
    return *(uint32_t*)&h;
}

// gemm tiles (BK=32, unchanged)
#define BK     32
#define TW     20
#define A_ST   (128 * TW)
#define W_ST   (64 * TW)
#define PIPE_BYTES (3 * (A_ST + W_ST) * 4)    // 46080
// conv tiles: BK=64, 2 stages
#define CTW    36
#define CA_ST  (128 * CTW)
#define CW_ST  (64 * CTW)
#define CPIPE_BYTES (2 * (CA_ST + CW_ST) * 4) // 55296

struct ConvP {
    int mb1, mb2;
    int s[3], k[3], w[3], o[3];
    const float* bias[3];
};
struct LnP {
    int r1, r2;
    const float *g[3], *b[3];
};
struct DwP {
    int e1, e2;
    int s[3], o[3];
    const float *w[3], *c[3];
};
struct AtP {
    int nkv[3], o[3];
};

// =====================================================================================
// Conversions
// =====================================================================================
__global__ void cvt_x_kernel(const float* __restrict__ in, __half* __restrict__ out, int n)
{
    int i = blockIdx.x * blockDim.x + threadIdx.x;
    if (i < n) out[i] = __float2half_rn(in[i]);
}

__global__ void cvt_w_kernel(const float* __restrict__ Wq, const float* __restrict__ Wkv,
                             const float* __restrict__ Wo, __half* __restrict__ wq,
                             __half* __restrict__ wkv, __half* __restrict__ wo)
{
    int i = blockIdx.x * blockDim.x + threadIdx.x;
    int total = 3 * C_ * C_;
    if (i >= total) return;
    int which = i / (C_ * C_);
    int r = i - which * (C_ * C_);
    int nn = r / C_, k = r - nn * C_;
    const float* src = (which == 0) ? Wq : (which == 1) ? Wkv : Wo;
    __half* dst = (which == 0) ? wq : (which == 1) ? wkv : wo;
    dst[nn * C_ + k] = __float2half_rn(src[(size_t)k * C_ + nn]);
}

__global__ void wtrans_all_kernel(const float* __restrict__ w1, const float* __restrict__ w2,
                                  const float* __restrict__ w3, __half* __restrict__ wt)
{
    const int CC = C_ * C_;
    int total = 84 * CC;
    for (int idx = blockIdx.x * blockDim.x + threadIdx.x; idx < total;
         idx += gridDim.x * blockDim.x) {
        const float* src;
        int rel, k2;
        if (idx < 64 * CC)      { src = w1; rel = idx;           k2 = 64; }
        else if (idx < 80 * CC) { src = w2; rel = idx - 64 * CC; k2 = 16; }
        else                    { src = w3; rel = idx - 80 * CC; k2 = 4;  }
        int ci = rel % C_;
        int rest = rel / C_;
        int co = rest % C_;
        int kyx = rest / C_;
        wt[idx] = __float2half_rn(src[((size_t)co * C_ + ci) * k2 + kyx]);
    }
}

// =====================================================================================
// Batched SR conv: BK=64, 2-stage cp.async. block 128x64, 4 warps (2m x 2n) of 64x32.
// =====================================================================================
__global__ __launch_bounds__(128) void conv_all_kernel(
    const __half* __restrict__ x, const __half* __restrict__ wtg,
    float* __restrict__ out, ConvP P)
{
    extern __shared__ uint32_t sm[];
    uint32_t* As = sm;                  // [2][128][CTW]
    uint32_t* Ws = sm + 2 * CA_ST;      // [2][64][CTW]

    const int tid = threadIdx.x;
    const int warp = tid >> 5, lane = tid & 31;
    const int wm = warp & 1, wn = warp >> 1;
    const int lr = lane >> 2, lc = lane & 3;
    const int b = blockIdx.z;
    const int n0 = blockIdx.y * 64;

    int bx = blockIdx.x;
    int br = (bx >= P.mb1) ? ((bx >= P.mb2) ? 2 : 1) : 0;
    int mblk = bx - ((br == 0) ? 0 : (br == 1) ? P.mb1 : P.mb2);
    const int s_ = P.s[br], ksz = P.k[br];
    const int n = s_ * s_;
    const int m0 = mblk * 128;
    const __half* wt = wtg + P.w[br];
    const float* bias = P.bias[br];
    float* ob = out + (size_t)(P.o[br]) * C_;

    const int prow8 = tid >> 3;         // 0..15
    const int ch = tid & 7;             // 16B chunk within 64-half row

    int rowoff[8];
    uint32_t amask = 0;
#pragma unroll
    for (int i = 0; i < 8; i++) {
        int p = m0 + prow8 + i * 16;
        if (p < n) amask |= (1u << i);
        int pp = (p < n) ? p : 0;
        rowoff[i] = ((pp / s_) * HW_ + (pp % s_)) * C_;
    }
    const __half* xb = x + (size_t)b * N_ * C_;

    const uint32_t asb = (uint32_t)__cvta_generic_to_shared(As);
    const uint32_t wsb = (uint32_t)__cvta_generic_to_shared(Ws);

    auto pf = [&](int kb, int st) {
        int kyx = kb / 3;
        int ci0 = (kb - kyx * 3) * 64;
        int ky = kyx / ksz, kx = kyx - ky * ksz;
        int koff = (ky * HW_ + kx) * C_ + ci0 + ch * 8;
#pragma unroll
        for (int i = 0; i < 8; i++)
            cp_async16(asb + (uint32_t)(((st * 128 + prow8 + i * 16) * CTW + ch * 4) * 4),
                       xb + rowoff[i] + koff,
                       ((amask >> i) & 1u) ? 16u : 0u);
        const __half* wp = wt + (size_t)kyx * C_ * C_ + ci0 + ch * 8;
#pragma unroll
        for (int i = 0; i < 4; i++) {
            int row = prow8 + i * 16;
            cp_async16(wsb + (uint32_t)(((st * 64 + row) * CTW + ch * 4) * 4),
                       wp + (size_t)(n0 + row) * C_, 16u);
        }
    };

    float acc[4][4][4];
#pragma unroll
    for (int mi = 0; mi < 4; mi++)
#pragma unroll
        for (int ni = 0; ni < 4; ni++)
#pragma unroll
            for (int j = 0; j < 4; j++) acc[mi][ni][j] = 0.f;

    const int KB = ksz * ksz * 3;
    pf(0, 0); cp_commit();

    for (int kb = 0; kb < KB; kb++) {
        int st = kb & 1;
        cp_wait0();
        __syncthreads();
        if (kb + 1 < KB) pf(kb + 1, st ^ 1);
        cp_commit();
        const uint32_t* as = As + st * CA_ST;
        const uint32_t* ws = Ws + st * CW_ST;
#pragma unroll
        for (int ks = 0; ks < 4; ks++) {
            int ksw = ks * 8;
            uint32_t af[4][4];
#pragma unroll
            for (int mi = 0; mi < 4; mi++) {
                int rr = wm * 64 + mi * 16 + lr;
                af[mi][0] = as[rr * CTW + ksw + lc];
                af[mi][1] = as[(rr + 8) * CTW + ksw + lc];
                af[mi][2] = as[rr * CTW + ksw + 4 + lc];
                af[mi][3] = as[(rr + 8) * CTW + ksw + 4 + lc];
            }
            uint32_t bf[4][2];
#pragma unroll
            for (int ni = 0; ni < 4; ni++) {
                int cc = wn * 32 + ni * 8 + lr;
                bf[ni][0] = ws[cc * CTW + ksw + lc];
                bf[ni][1] = ws[cc * CTW + ksw + 4 + lc];
            }
#pragma unroll
            for (int mi = 0; mi < 4; mi++)
#pragma unroll
                for (int ni = 0; ni < 4; ni++) mma_f16(acc[mi][ni], af[mi], bf[ni]);
        }
    }
#pragma unroll
    for (int mi = 0; mi < 4; mi++) {
        int row = m0 + wm * 64 + mi * 16 + lr;
#pragma unroll
        for (int ni = 0; ni < 4; ni++) {
            int col = n0 + wn * 32 + ni * 8 + lc * 2;
            float b0 = bias[col], b1 = bias[col + 1];
            if (row < n) {
                float* o = ob + ((size_t)b * n + row) * C_ + col;
                o[0] = acc[mi][ni][0] + b0;
                o[1] = acc[mi][ni][1] + b1;
            }
            if (row + 8 < n) {
                float* o = ob + ((size_t)b * n + row + 8) * C_ + col;
                o[0] = acc[mi][ni][2] + b0;
                o[1] = acc[mi][ni][3] + b1;
            }
        }
    }
}

// =====================================================================================
// FP16 TC GEMM (unchanged): tiles 128x64, 8 warps 32x32.
// =====================================================================================
__global__ __launch_bounds__(256) void gemm_tc_kernel(
    const __half* __restrict__ A, const __half* __restrict__ W,
    const float* __restrict__ bias, float* __restrict__ out,
    int M, int K, int ldc)
{
    extern __shared__ uint32_t sm[];
    uint32_t* As = sm;
    uint32_t* Ws = sm + 3 * A_ST;

    const int tid = threadIdx.x;
    const int warp = tid >> 5, lane = tid & 31;
    const int wm = warp & 3, wn = warp >> 2;
    const int lr = lane >> 2, lc = lane & 3;
    const int m0 = blockIdx.x * 128;
    const int n0 = blockIdx.y * 64;

    const int r6 = tid >> 2;
    const int chk = tid & 3;

    const __half* aPtr[2];
    uint32_t aSz[2];
#pragma unroll
    for (int i = 0; i < 2; i++) {
        int m = m0 + r6 + i * 64;
        aSz[i] = (m < M) ? 16u : 0u;
        aPtr[i] = A + (size_t)((m < M) ? m : 0) * K + chk * 8;
    }
    const __half* wPtr = W + (size_t)(n0 + r6) * K + chk * 8;

    const uint32_t asb = (uint32_t)__cvta_generic_to_shared(As);
    const uint32_t wsb = (uint32_t)__cvta_generic_to_shared(Ws);

    auto pf = [&](int kb, int st) {
        int k0 = kb * BK;
#pragma unroll
        for (int i = 0; i < 2; i++)
            cp_async16(asb + (uint32_t)(((st * 128 + r6 + i * 64) * TW + chk * 4) * 4),
                       aPtr[i] + k0, aSz[i]);
        cp_async16(wsb + (uint32_t)(((st * 64 + r6) * TW + chk * 4) * 4), wPtr + k0, 16u);
    };

    float acc[2][4][4];
#pragma unroll
    for (int mi = 0; mi < 2; mi++)
#pragma unroll
        for (int ni = 0; ni < 4; ni++)
#pragma unroll
            for (int j = 0; j < 4; j++) acc[mi][ni][j] = 0.f;

    const int KB = K / BK;
    pf(0, 0); cp_commit();
    pf(1, 1); cp_commit();

    int st = 0;
    for (int kb = 0; kb < KB; kb++) {
        if (kb + 1 < KB) cp_wait1(); else cp_wait0();
        __syncthreads();
        if (kb + 2 < KB) pf(kb + 2, (st + 2) % 3);
        cp_commit();
        const uint32_t* as = As + st * A_ST;
        const uint32_t* ws = Ws + st * W_ST;
#pragma unroll
        for (int ks = 0; ks < 2; ks++) {
            int ksw = ks * 8;
            uint32_t af[2][4];
#pragma unroll
            for (int mi = 0; mi < 2; mi++) {
                int rr = wm * 32 + mi * 16 + lr;
                af[mi][0] = as[rr * TW + ksw + lc];
                af[mi][1] = as[(rr + 8) * TW + ksw + lc];
                af[mi][2] = as[rr * TW + ksw + 4 + lc];
                af[mi][3] = as[(rr + 8) * TW + ksw + 4 + lc];
            }
            uint32_t bf[4][2];
#pragma unroll
            for (int ni = 0; ni < 4; ni++) {
                int cc = wn * 32 + ni * 8 + lr;
                bf[ni][0] = ws[cc * TW + ksw + lc];
                bf[ni][1] = ws[cc * TW + ksw + 4 + lc];
            }
#pragma unroll
            for (int mi = 0; mi < 2; mi++)
#pragma unroll
                for (int ni = 0; ni < 4; ni++) mma_f16(acc[mi][ni], af[mi], bf[ni]);
        }
        st = (st + 1) % 3;
    }
#pragma unroll
    for (int mi = 0; mi < 2; mi++) {
        int row = m0 + wm * 32 + mi * 16 + lr;
#pragma unroll
        for (int ni = 0; ni < 4; ni++) {
            int col = n0 + wn * 32 + ni * 8 + lc * 2;
            float b0 = bias[col], b1 = bias[col + 1];
            if (row < M) {
                out[(size_t)row * ldc + col]     = acc[mi][ni][0] + b0;
                out[(size_t)row * ldc + col + 1] = acc[mi][ni][1] + b1;
            }
            if (row + 8 < M) {
                out[(size_t)(row + 8) * ldc + col]     = acc[mi][ni][2] + b0;
                out[(size_t)(row + 8) * ldc + col + 1] = acc[mi][ni][3] + b1;
            }
        }
    }
}

// =====================================================================================
// Batched LayerNorm + exact GELU. One warp per row.
// =====================================================================================
__global__ void ln_gelu_all_kernel(const float* __restrict__ xr, __half* __restrict__ xrh,
                                   LnP P, int rows)
{
    int wid = (blockIdx.x * blockDim.x + threadIdx.x) >> 5;
    int lane = threadIdx.x & 31;
    if (wid >= rows) return;
    int br = (wid >= P.r1) ? ((wid >= P.r2) ? 2 : 1) : 0;
    const float* g = P.g[br];
    const float* bb = P.b[br];
    const float* row = xr + (size_t)wid * C_;
    __half* orow = xrh + (size_t)wid * C_;
    float s1 = 0.f, s2 = 0.f;
#pragma unroll
    for (int j = lane; j < C_; j += 32) {
        float v = row[j];
        s1 += v;
        s2 += v * v;
    }
#pragma unroll
    for (int o = 16; o; o >>= 1) {
        s1 += __shfl_xor_sync(0xffffffffu, s1, o);
        s2 += __shfl_xor_sync(0xffffffffu, s2, o);
    }
    float mu = s1 * (1.f / C_);
    float var = s2 * (1.f / C_) - mu * mu;
    float inv = rsqrtf(var + 1e-5f);
#pragma unroll
    for (int j = lane; j < C_; j += 32) {
        float v = (row[j] - mu) * inv * g[j] + bb[j];
        orow[j] = __float2half_rn(0.5f * v * (1.f + erff(v * 0.70710678118654752440f)));
    }
}

// =====================================================================================
// Batched depthwise 3x3 + residual; writes TRANSPOSED v2t[d][row].
// =====================================================================================
__global__ void dwconv_all_kernel(const float* __restrict__ kv, float* __restrict__ v2t,
                                  DwP P, int total)
{
    int idx = blockIdx.x * blockDim.x + threadIdx.x;
    if (idx >= total) return;
    int br = (idx >= P.e1) ? ((idx >= P.e2) ? 2 : 1) : 0;
    int local = idx - ((br == 0) ? 0 : (br == 1) ? P.e1 : P.e2);
    int s = P.s[br];
    int n = s * s;
    const float* w = P.w[br];
    const float* bias = P.c[br];
    int hd = local & 63;
    int p = (local >> 6) % n;
    int b = (local >> 6) / n;
    int y = p / s;
    int x0 = p - y * s;
    size_t base = (size_t)(P.o[br] + b * n);
    const float* vb = kv + base * 128 + 64 + hd;
    float acc = bias[hd];
#pragma unroll
    for (int dy = -1; dy <= 1; dy++) {
#pragma unroll
        for (int dx = -1; dx <= 1; dx++) {
            int yy = y + dy, xx = x0 + dx;
            if (yy >= 0 && yy < s && xx >= 0 && xx < s)
                acc += w[hd * 9 + (dy + 1) * 3 + (dx + 1)] * vb[(size_t)(yy * s + xx) * 128];
        }
    }
    v2t[(size_t)hd * RTOT_ + base + p] = acc + vb[(size_t)p * 128];
}

// =====================================================================================
// Batched flash attention, FULL FP16 MMA (m16n8k16), fp32 softmax/accum.
// Static smem: qs/kst [row|key][72 halves d-major], vs [d][72 halves key-major],
// ps [row][72 halves key-major]. All stride 36 words -> conflict-free frags.
// =====================================================================================
__global__ __launch_bounds__(128) void attn_all_kernel(
    const float* __restrict__ q, const float* __restrict__ kv,
    const float* __restrict__ v2t, __half* __restrict__ xcath, AtP P)
{
    __shared__ uint32_t qsw[64 * 36];
    __shared__ uint32_t kstw[64 * 36];
    __shared__ uint32_t vsw[64 * 36];
    __shared__ uint32_t psw[64 * 36];

    const int tid = threadIdx.x;
    const int warp = tid >> 5, lane = tid & 31;
    const int wm = warp;
    const int lr = lane >> 2, lc = lane & 3;
    const int b = blockIdx.y;
    const int head = blockIdx.z;
    const int q0 = blockIdx.x * 64;
    const int rr = wm * 16 + lr;
    const int nkv = P.nkv[head];
    const float* kvb = kv + (size_t)P.o[head] * 128;
    const float scale = 0.07216878364870322056f;  // 1/sqrt(192)

    // Q tile: rows q0..q0+63, 32 words of packed d
#pragma unroll
    for (int i = 0; i < 16; i++) {
        int e = tid + i * 128;
        int r = e >> 5, w = e & 31;
        const float* qp = q + ((size_t)b * N_ + q0 + r) * C_ + head * HD_ + 2 * w;
        float2 f = *(const float2*)qp;
        qsw[r * 36 + w] = packh2(f.x, f.y);
    }

    float m_i[2], l_i[2], oacc[8][4];
    m_i[0] = m_i[1] = -1e30f;
    l_i[0] = l_i[1] = 0.f;
#pragma unroll
    for (int ni = 0; ni < 8; ni++)
#pragma unroll
        for (int j = 0; j < 4; j++) oacc[ni][j] = 0.f;

    __syncthreads();

    const int nchunks = (nkv + 63) >> 6;
    for (int c0 = 0; c0 < nchunks; c0++) {
        int base = c0 * 64;
        int cs = nkv - base;
        if (cs > 64) cs = 64;
        // K: [key][d packed]
#pragma unroll
        for (int i = 0; i < 16; i++) {
            int e = tid + i * 128;
            int r = e >> 5, w = e & 31;
            uint32_t v = 0u;
            if (r < cs) {
                const float* kp = kvb + ((size_t)b * nkv + base + r) * 128 + 2 * w;
                float2 f = *(const float2*)kp;
                v = packh2(f.x, f.y);
            }
            kstw[r * 36 + w] = v;
        }
        // V: [d][key packed] from transposed v2t (scalar loads: parity of base varies)
        {
            const float* v2d = v2t + (size_t)P.o[head] + (size_t)b * nkv + base;
#pragma unroll
            for (int i = 0; i < 16; i++) {
                int e = tid + i * 128;
                int d = e >> 5, w = e & 31;
                int k0 = 2 * w, k1 = 2 * w + 1;
                const float* vp = v2d + (size_t)d * RTOT_;
                float f0 = (k0 < cs) ? vp[k0] : 0.f;
                float f1 = (k1 < cs) ? vp[k1] : 0.f;
                vsw[d * 36 + w] = packh2(f0, f1);
            }
        }
        __syncthreads();

        // S = Q @ K^T : 4 k16-steps
        float sacc[8][4];
#pragma unroll
        for (int ni = 0; ni < 8; ni++)
#pragma unroll
            for (int j = 0; j < 4; j++) sacc[ni][j] = 0.f;
#pragma unroll
        for (int ks = 0; ks < 4; ks++) {
            int ksw = ks * 8;
            uint32_t af[4];
            af[0] = qsw[rr * 36 + ksw + lc];
            af[1] = qsw[(rr + 8) * 36 + ksw + lc];
            af[2] = qsw[rr * 36 + ksw + 4 + lc];
            af[3] = qsw[(rr + 8) * 36 + ksw + 4 + lc];
#pragma unroll
            for (int ni = 0; ni < 8; ni++) {
                int cc = ni * 8 + lr;
                uint32_t bf[2];
                bf[0] = kstw[cc * 36 + ksw + lc];
                bf[1] = kstw[cc * 36 + ksw + 4 + lc];
                mma_f16(sacc[ni], af, bf);
            }
        }

        // online softmax (rows rr and rr+8)
#pragma unroll
        for (int h = 0; h < 2; h++) {
            float mx = -1e30f;
#pragma unroll
            for (int ni = 0; ni < 8; ni++)
#pragma unroll
                for (int j = 0; j < 2; j++) {
                    float v = sacc[ni][2 * h + j] * scale;
                    if (ni * 8 + 2 * lc + j >= cs) v = -1e30f;
                    sacc[ni][2 * h + j] = v;
                    mx = fmaxf(mx, v);
                }
            mx = fmaxf(mx, __shfl_xor_sync(0xffffffffu, mx, 1));
            mx = fmaxf(mx, __shfl_xor_sync(0xffffffffu, mx, 2));
            float mnew = fmaxf(m_i[h], mx);
            float alpha = __expf(m_i[h] - mnew);
            float rs = 0.f;
#pragma unroll
            for (int ni = 0; ni < 8; ni++)
#pragma unroll
                for (int j = 0; j < 2; j++) {
                    float p = __expf(sacc[ni][2 * h + j] - mnew);
                    sacc[ni][2 * h + j] = p;
                    rs += p;
                }
            rs += __shfl_xor_sync(0xffffffffu, rs, 1);
            rs += __shfl_xor_sync(0xffffffffu, rs, 2);
            l_i[h] = l_i[h] * alpha + rs;
            m_i[h] = mnew;
#pragma unroll
            for (int ni = 0; ni < 8; ni++) {
                oacc[ni][2 * h]     *= alpha;
                oacc[ni][2 * h + 1] *= alpha;
            }
        }

        // P -> smem as packed half2 (A operand of P@V); warp-private rows
#pragma unroll
        for (int ni = 0; ni < 8; ni++) {
            int wdx = ni * 4 + lc;
            psw[rr * 36 + wdx]       = packh2(sacc[ni][0], sacc[ni][1]);
            psw[(rr + 8) * 36 + wdx] = packh2(sacc[ni][2], sacc[ni][3]);
        }
        __syncwarp();

        // O += P @ V : 4 k16-steps over keys
#pragma unroll
        for (int ks = 0; ks < 4; ks++) {
            int ksw = ks * 8;
            uint32_t af[4];
            af[0] = psw[rr * 36 + ksw + lc];
            af[1] = psw[(rr + 8) * 36 + ksw + lc];
            af[2] = psw[rr * 36 + ksw + 4 + lc];
            af[3] = psw[(rr + 8) * 36 + ksw + 4 + lc];
#pragma unroll
            for (int ni = 0; ni < 8; ni++) {
                int cc = ni * 8 + lr;
                uint32_t bf[2];
                bf[0] = vsw[cc * 36 + ksw + lc];
                bf[1] = vsw[cc * 36 + ksw + 4 + lc];
                mma_f16(oacc[ni], af, bf);
            }
        }
        __syncthreads();
    }

    float inv0 = 1.f / l_i[0], inv1 = 1.f / l_i[1];
#pragma unroll
    for (int ni = 0; ni < 8; ni++) {
        int col = head * HD_ + ni * 8 + 2 * lc;
        size_t r0 = (size_t)b * N_ + q0 + rr;
        *(__half2*)(xcath + r0 * C_ + col) =
            __floats2half2_rn(oacc[ni][0] * inv0, oacc[ni][1] * inv0);
        *(__half2*)(xcath + (r0 + 8) * C_ + col) =
            __floats2half2_rn(oacc[ni][2] * inv1, oacc[ni][3] * inv1);
    }
}

// =====================================================================================
// Host orchestration: conv_all at profiled launch index 3.
// =====================================================================================
extern "C" void kernel_launch(void* const* d_in, const int* in_sizes, int n_in,
                              void* d_out, int out_size)
{
    const float* x   = (const float*)d_in[0];
    const float* Wq  = (const float*)d_in[1];
    const float* bq  = (const float*)d_in[2];
    const float* Wkv = (const float*)d_in[3];
    const float* bkv = (const float*)d_in[4];
    const float* Wo  = (const float*)d_in[23];
    const float* bo  = (const float*)d_in[24];

    float *q, *xr, *kvb, *v2t;
    __half *xh, *xrh, *xcath, *wth, *wqh, *wkvh, *woh;
    cudaGetSymbolAddress((void**)&q, g_q);
    cudaGetSymbolAddress((void**)&xr, g_xr);
    cudaGetSymbolAddress((void**)&kvb, g_kv);
    cudaGetSymbolAddress((void**)&v2t, g_v2t);
    cudaGetSymbolAddress((void**)&xh, g_xh);
    cudaGetSymbolAddress((void**)&xrh, g_xrh);
    cudaGetSymbolAddress((void**)&xcath, g_xcath);
    cudaGetSymbolAddress((void**)&wth, g_wth);
    cudaGetSymbolAddress((void**)&wqh, g_wqh);
    cudaGetSymbolAddress((void**)&wkvh, g_wkvh);
    cudaGetSymbolAddress((void**)&woh, g_woh);

    cudaFuncSetAttribute(gemm_tc_kernel, cudaFuncAttributeMaxDynamicSharedMemorySize,
                         PIPE_BYTES);
    cudaFuncSetAttribute(conv_all_kernel, cudaFuncAttributeMaxDynamicSharedMemorySize,
                         CPIPE_BYTES);

    const int M = B_ * N_;
    const int NX = B_ * N_ * C_;
    const int CC = C_ * C_;

    const int sA = 41, sB = 45, sC = 47;
    const int nA = sA * sA, nB = sB * sB, nC = sC * sC;
    const int oA = 0, oB = B_ * nA, oC = B_ * (nA + nB);
    const int rows = RTOT_;

    ConvP cp;
    cp.mb1 = (nA + 127) / 128;
    cp.mb2 = cp.mb1 + (nB + 127) / 128;
    int nblk = cp.mb2 + (nC + 127) / 128;
    cp.s[0] = sA; cp.s[1] = sB; cp.s[2] = sC;
    cp.k[0] = 8;  cp.k[1] = 4;  cp.k[2] = 2;
    cp.w[0] = 0;  cp.w[1] = 64 * CC; cp.w[2] = 80 * CC;
    cp.o[0] = oA; cp.o[1] = oB; cp.o[2] = oC;
    cp.bias[0] = (const float*)d_in[6];
    cp.bias[1] = (const float*)d_in[12];
    cp.bias[2] = (const float*)d_in[18];

    LnP lp;
    lp.r1 = oB; lp.r2 = oC;
    lp.g[0] = (const float*)d_in[7];  lp.b[0] = (const float*)d_in[8];
    lp.g[1] = (const float*)d_in[13]; lp.b[1] = (const float*)d_in[14];
    lp.g[2] = (const float*)d_in[19]; lp.b[2] = (const float*)d_in[20];

    DwP dp;
    dp.e1 = oB * 64; dp.e2 = oC * 64;
    dp.s[0] = sA; dp.s[1] = sB; dp.s[2] = sC;
    dp.o[0] = oA; dp.o[1] = oB; dp.o[2] = oC;
    dp.w[0] = (const float*)d_in[9];  dp.c[0] = (const float*)d_in[10];
    dp.w[1] = (const float*)d_in[15]; dp.c[1] = (const float*)d_in[16];
    dp.w[2] = (const float*)d_in[21]; dp.c[2] = (const float*)d_in[22];

    AtP ap;
    ap.nkv[0] = nA; ap.nkv[1] = nB; ap.nkv[2] = nC;
    ap.o[0] = oA; ap.o[1] = oB; ap.o[2] = oC;

    // 0
    cvt_x_kernel<<<(NX + 255) / 256, 256>>>(x, xh, NX);
    // 1
    cvt_w_kernel<<<(3 * CC + 255) / 256, 256>>>(Wq, Wkv, Wo, wqh, wkvh, woh);
    // 2
    wtrans_all_kernel<<<512, 256>>>((const float*)d_in[5], (const float*)d_in[11],
                                    (const float*)d_in[17], wth);
    // 3 (PROFILED): all SR convs
    conv_all_kernel<<<dim3(nblk, 3, B_), 128, CPIPE_BYTES>>>(xh, wth, xr, cp);
    // 4
    gemm_tc_kernel<<<dim3((M + 127) / 128, 3), 256, PIPE_BYTES>>>(
        xh, wqh, bq, q, M, C_, C_);
    // 5
    ln_gelu_all_kernel<<<(rows + 7) / 8, 256>>>(xr, xrh, lp, rows);
    // 6
    gemm_tc_kernel<<<dim3((rows + 127) / 128, 2), 256, PIPE_BYTES>>>(
        xrh, wkvh, bkv, kvb, rows, C_, 128);
    // 7
    dwconv_all_kernel<<<(rows * 64 + 255) / 256, 256>>>(kvb, v2t, dp, rows * 64);
    // 8
    attn_all_kernel<<<dim3(N_ / 64, B_, 3), 128>>>(q, kvb, v2t, xcath, ap);
    // 9
    gemm_tc_kernel<<<dim3((M + 127) / 128, 3), 256, PIPE_BYTES>>>(
        xcath, woh, bo, (float*)d_out, M, C_, C_);
}

// round 17
// speedup vs baseline: 1.0070x; 1.0070x over previous
#include <cuda_runtime.h>
#include <cuda_fp16.h>
#include <math.h>
#include <stdint.h>

#define B_    8
#define N_    2304
#define C_    192
#define HW_   48
#define HD_   64
#define NTOT_ 5915
#define RTOT_ (B_ * NTOT_)        // 47320

// ---------------- scratch ----------------
__device__ float  g_q[B_ * N_ * C_];
__device__ float  g_xr[RTOT_ * C_];
__device__ float  g_kv[RTOT_ * 128];
__device__ float  g_v2t[HD_ * RTOT_];        // TRANSPOSED: [d][row]
__device__ __half g_xh[B_ * N_ * C_];
__device__ __half g_xrh[RTOT_ * C_];
__device__ __half g_xcath[B_ * N_ * C_];
__device__ __half g_wth[C_ * C_ * 84];
__device__ __half g_wqh[C_ * C_];
__device__ __half g_wkvh[C_ * C_];
__device__ __half g_woh[C_ * C_];

// ---------------- helpers ----------------
__device__ __forceinline__ void mma_f16(float* d, const uint32_t* a, const uint32_t* b) {
    asm volatile(
        "mma.sync.aligned.m16n8k16.row.col.f32.f16.f16.f32 "
        "{%0,%1,%2,%3}, {%4,%5,%6,%7}, {%8,%9}, {%0,%1,%2,%3};"
        : "+f"(d[0]), "+f"(d[1]), "+f"(d[2]), "+f"(d[3])
        : "r"(a[0]), "r"(a[1]), "r"(a[2]), "r"(a[3]), "r"(b[0]), "r"(b[1]));
}
__device__ __forceinline__ void cp_async16(uint32_t dst, const void* src, uint32_t ssize) {
    asm volatile("cp.async.cg.shared.global [%0], [%1], 16, %2;"
                 :: "r"(dst), "l"(src), "r"(ssize) : "memory");
}
__device__ __forceinline__ void cp_commit() {
    asm volatile("cp.async.commit_group;" ::: "memory");
}
__device__ __forceinline__ void cp_wait1() {
    asm volatile("cp.async.wait_group 1;" ::: "memory");
}
__device__ __forceinline__ void cp_wait0() {
    asm volatile("cp.async.wait_group 0;" ::: "memory");
}
__device__ __forceinline__ uint32_t packh2(float a, float b) {
    __half2 h = __floats2half2_rn(a, b);
    return *(uint32_t*)&h;
}

// gemm tiles (BK=32, unchanged)
#define BK     32
#define TW     20
#define A_ST   (128 * TW)
#define W_ST   (64 * TW)
#define PIPE_BYTES (3 * (A_ST + W_ST) * 4)    // 46080
// conv tiles: BK=64, 2 stages
#define CTW    36
#define CA_ST  (128 * CTW)
#define CW_ST  (64 * CTW)
#define CPIPE_BYTES (2 * (CA_ST + CW_ST) * 4) // 55296

struct ConvP {
    int mb1, mb2;
    int s[3], k[3], w[3], o[3];
    const float* bias[3];
};
struct LnP {
    int r1, r2;
    const float *g[3], *b[3];
};
struct DwP {
    int e1, e2;
    int s[3], o[3];
    const float *w[3], *c[3];
};
struct AtP {
    int nkv[3], o[3];
};

// =====================================================================================
// Conversions
// =====================================================================================
__global__ void cvt_x_kernel(const float* __restrict__ in, __half* __restrict__ out, int n)
{
    int i = blockIdx.x * blockDim.x + threadIdx.x;
    if (i < n) out[i] = __float2half_rn(in[i]);
}

__global__ void cvt_w_kernel(const float* __restrict__ Wq, const float* __restrict__ Wkv,
                             const float* __restrict__ Wo, __half* __restrict__ wq,
                             __half* __restrict__ wkv, __half* __restrict__ wo)
{
    int i = blockIdx.x * blockDim.x + threadIdx.x;
    int total = 3 * C_ * C_;
    if (i >= total) return;
    int which = i / (C_ * C_);
    int r = i - which * (C_ * C_);
    int nn = r / C_, k = r - nn * C_;
    const float* src = (which == 0) ? Wq : (which == 1) ? Wkv : Wo;
    __half* dst = (which == 0) ? wq : (which == 1) ? wkv : wo;
    dst[nn * C_ + k] = __float2half_rn(src[(size_t)k * C_ + nn]);
}

__global__ void wtrans_all_kernel(const float* __restrict__ w1, const float* __restrict__ w2,
                                  const float* __restrict__ w3, __half* __restrict__ wt)
{
    const int CC = C_ * C_;
    int total = 84 * CC;
    for (int idx = blockIdx.x * blockDim.x + threadIdx.x; idx < total;
         idx += gridDim.x * blockDim.x) {
        const float* src;
        int rel, k2;
        if (idx < 64 * CC)      { src = w1; rel = idx;           k2 = 64; }
        else if (idx < 80 * CC) { src = w2; rel = idx - 64 * CC; k2 = 16; }
        else                    { src = w3; rel = idx - 80 * CC; k2 = 4;  }
        int ci = rel % C_;
        int rest = rel / C_;
        int co = rest % C_;
        int kyx = rest / C_;
        wt[idx] = __float2half_rn(src[((size_t)co * C_ + ci) * k2 + kyx]);
    }
}

// =====================================================================================
// Batched SR conv: BK=64, 2-stage cp.async. block 128x64, 4 warps (2m x 2n) of 64x32.
// =====================================================================================
__global__ __launch_bounds__(128) void conv_all_kernel(
    const __half* __restrict__ x, const __half* __restrict__ wtg,
    float* __restrict__ out, ConvP P)
{
    extern __shared__ uint32_t sm[];
    uint32_t* As = sm;                  // [2][128][CTW]
    uint32_t* Ws = sm + 2 * CA_ST;      // [2][64][CTW]

    const int tid = threadIdx.x;
    const int warp = tid >> 5, lane = tid & 31;
    const int wm = warp & 1, wn = warp >> 1;
    const int lr = lane >> 2, lc = lane & 3;
    const int b = blockIdx.z;
    const int n0 = blockIdx.y * 64;

    int bx = blockIdx.x;
    int br = (bx >= P.mb1) ? ((bx >= P.mb2) ? 2 : 1) : 0;
    int mblk = bx - ((br == 0) ? 0 : (br == 1) ? P.mb1 : P.mb2);
    const int s_ = P.s[br], ksz = P.k[br];
    const int n = s_ * s_;
    const int m0 = mblk * 128;
    const __half* wt = wtg + P.w[br];
    const float* bias = P.bias[br];
    float* ob = out + (size_t)(P.o[br]) * C_;

    const int prow8 = tid >> 3;         // 0..15
    const int ch = tid & 7;             // 16B chunk within 64-half row

    int rowoff[8];
    uint32_t amask = 0;
#pragma unroll
    for (int i = 0; i < 8; i++) {
        int p = m0 + prow8 + i * 16;
        if (p < n) amask |= (1u << i);
        int pp = (p < n) ? p : 0;
        rowoff[i] = ((pp / s_) * HW_ + (pp % s_)) * C_;
    }
    const __half* xb = x + (size_t)b * N_ * C_;

    const uint32_t asb = (uint32_t)__cvta_generic_to_shared(As);
    const uint32_t wsb = (uint32_t)__cvta_generic_to_shared(Ws);

    auto pf = [&](int kb, int st) {
        int kyx = kb / 3;
        int ci0 = (kb - kyx * 3) * 64;
        int ky = kyx / ksz, kx = kyx - ky * ksz;
        int koff = (ky * HW_ + kx) * C_ + ci0 + ch * 8;
#pragma unroll
        for (int i = 0; i < 8; i++)
            cp_async16(asb + (uint32_t)(((st * 128 + prow8 + i * 16) * CTW + ch * 4) * 4),
                       xb + rowoff[i] + koff,
                       ((amask >> i) & 1u) ? 16u : 0u);
        const __half* wp = wt + (size_t)kyx * C_ * C_ + ci0 + ch * 8;
#pragma unroll
        for (int i = 0; i < 4; i++) {
            int row = prow8 + i * 16;
            cp_async16(wsb + (uint32_t)(((st * 64 + row) * CTW + ch * 4) * 4),
                       wp + (size_t)(n0 + row) * C_, 16u);
        }
    };

    float acc[4][4][4];
#pragma unroll
    for (int mi = 0; mi < 4; mi++)
#pragma unroll
        for (int ni = 0; ni < 4; ni++)
#pragma unroll
            for (int j = 0; j < 4; j++) acc[mi][ni][j] = 0.f;

    const int KB = ksz * ksz * 3;
    pf(0, 0); cp_commit();

    for (int kb = 0; kb < KB; kb++) {
        int st = kb & 1;
        cp_wait0();
        __syncthreads();
        if (kb + 1 < KB) pf(kb + 1, st ^ 1);
        cp_commit();
        const uint32_t* as = As + st * CA_ST;
        const uint32_t* ws = Ws + st * CW_ST;
#pragma unroll
        for (int ks = 0; ks < 4; ks++) {
            int ksw = ks * 8;
            uint32_t af[4][4];
#pragma unroll
            for (int mi = 0; mi < 4; mi++) {
                int rr = wm * 64 + mi * 16 + lr;
                af[mi][0] = as[rr * CTW + ksw + lc];
                af[mi][1] = as[(rr + 8) * CTW + ksw + lc];
                af[mi][2] = as[rr * CTW + ksw + 4 + lc];
                af[mi][3] = as[(rr + 8) * CTW + ksw + 4 + lc];
            }
            uint32_t bf[4][2];
#pragma unroll
            for (int ni = 0; ni < 4; ni++) {
                int cc = wn * 32 + ni * 8 + lr;
                bf[ni][0] = ws[cc * CTW + ksw + lc];
                bf[ni][1] = ws[cc * CTW + ksw + 4 + lc];
            }
#pragma unroll
            for (int mi = 0; mi < 4; mi++)
#pragma unroll
                for (int ni = 0; ni < 4; ni++) mma_f16(acc[mi][ni], af[mi], bf[ni]);
        }
    }
#pragma unroll
    for (int mi = 0; mi < 4; mi++) {
        int row = m0 + wm * 64 + mi * 16 + lr;
#pragma unroll
        for (int ni = 0; ni < 4; ni++) {
            int col = n0 + wn * 32 + ni * 8 + lc * 2;
            float b0 = bias[col], b1 = bias[col + 1];
            if (row < n) {
                float* o = ob + ((size_t)b * n + row) * C_ + col;
                o[0] = acc[mi][ni][0] + b0;
                o[1] = acc[mi][ni][1] + b1;
            }
            if (row + 8 < n) {
                float* o = ob + ((size_t)b * n + row + 8) * C_ + col;
                o[0] = acc[mi][ni][2] + b0;
                o[1] = acc[mi][ni][3] + b1;
            }
        }
    }
}

// =====================================================================================
// FP16 TC GEMM (unchanged): tiles 128x64, 8 warps 32x32.
// =====================================================================================
__global__ __launch_bounds__(256) void gemm_tc_kernel(
    const __half* __restrict__ A, const __half* __restrict__ W,
    const float* __restrict__ bias, float* __restrict__ out,
    int M, int K, int ldc)
{
    extern __shared__ uint32_t sm[];
    uint32_t* As = sm;
    uint32_t* Ws = sm + 3 * A_ST;

    const int tid = threadIdx.x;
    const int warp = tid >> 5, lane = tid & 31;
    const int wm = warp & 3, wn = warp >> 2;
    const int lr = lane >> 2, lc = lane & 3;
    const int m0 = blockIdx.x * 128;
    const int n0 = blockIdx.y * 64;

    const int r6 = tid >> 2;
    const int chk = tid & 3;

    const __half* aPtr[2];
    uint32_t aSz[2];
#pragma unroll
    for (int i = 0; i < 2; i++) {
        int m = m0 + r6 + i * 64;
        aSz[i] = (m < M) ? 16u : 0u;
        aPtr[i] = A + (size_t)((m < M) ? m : 0) * K + chk * 8;
    }
    const __half* wPtr = W + (size_t)(n0 + r6) * K + chk * 8;

    const uint32_t asb = (uint32_t)__cvta_generic_to_shared(As);
    const uint32_t wsb = (uint32_t)__cvta_generic_to_shared(Ws);

    auto pf = [&](int kb, int st) {
        int k0 = kb * BK;
#pragma unroll
        for (int i = 0; i < 2; i++)
            cp_async16(asb + (uint32_t)(((st * 128 + r6 + i * 64) * TW + chk * 4) * 4),
                       aPtr[i] + k0, aSz[i]);
        cp_async16(wsb + (uint32_t)(((st * 64 + r6) * TW + chk * 4) * 4), wPtr + k0, 16u);
    };

    float acc[2][4][4];
#pragma unroll
    for (int mi = 0; mi < 2; mi++)
#pragma unroll
        for (int ni = 0; ni < 4; ni++)
#pragma unroll
            for (int j = 0; j < 4; j++) acc[mi][ni][j] = 0.f;

    const int KB = K / BK;
    pf(0, 0); cp_commit();
    pf(1, 1); cp_commit();

    int st = 0;
    for (int kb = 0; kb < KB; kb++) {
        if (kb + 1 < KB) cp_wait1(); else cp_wait0();
        __syncthreads();
        if (kb + 2 < KB) pf(kb + 2, (st + 2) % 3);
        cp_commit();
        const uint32_t* as = As + st * A_ST;
        const uint32_t* ws = Ws + st * W_ST;
#pragma unroll
        for (int ks = 0; ks < 2; ks++) {
            int ksw = ks * 8;
            uint32_t af[2][4];
#pragma unroll
            for (int mi = 0; mi < 2; mi++) {
                int rr = wm * 32 + mi * 16 + lr;
                af[mi][0] = as[rr * TW + ksw + lc];
                af[mi][1] = as[(rr + 8) * TW + ksw + lc];
                af[mi][2] = as[rr * TW + ksw + 4 + lc];
                af[mi][3] = as[(rr + 8) * TW + ksw + 4 + lc];
            }
            uint32_t bf[4][2];
#pragma unroll
            for (int ni = 0; ni < 4; ni++) {
                int cc = wn * 32 + ni * 8 + lr;
                bf[ni][0] = ws[cc * TW + ksw + lc];
                bf[ni][1] = ws[cc * TW + ksw + 4 + lc];
            }
#pragma unroll
            for (int mi = 0; mi < 2; mi++)
#pragma unroll
                for (int ni = 0; ni < 4; ni++) mma_f16(acc[mi][ni], af[mi], bf[ni]);
        }
        st = (st + 1) % 3;
    }
#pragma unroll
    for (int mi = 0; mi < 2; mi++) {
        int row = m0 + wm * 32 + mi * 16 + lr;
#pragma unroll
        for (int ni = 0; ni < 4; ni++) {
            int col = n0 + wn * 32 + ni * 8 + lc * 2;
            float b0 = bias[col], b1 = bias[col + 1];
            if (row < M) {
                out[(size_t)row * ldc + col]     = acc[mi][ni][0] + b0;
                out[(size_t)row * ldc + col + 1] = acc[mi][ni][1] + b1;
            }
            if (row + 8 < M) {
                out[(size_t)(row + 8) * ldc + col]     = acc[mi][ni][2] + b0;
                out[(size_t)(row + 8) * ldc + col + 1] = acc[mi][ni][3] + b1;
            }
        }
    }
}

// =====================================================================================
// Batched LayerNorm + exact GELU. One warp per row.
// =====================================================================================
__global__ void ln_gelu_all_kernel(const float* __restrict__ xr, __half* __restrict__ xrh,
                                   LnP P, int rows)
{
    int wid = (blockIdx.x * blockDim.x + threadIdx.x) >> 5;
    int lane = threadIdx.x & 31;
    if (wid >= rows) return;
    int br = (wid >= P.r1) ? ((wid >= P.r2) ? 2 : 1) : 0;
    const float* g = P.g[br];
    const float* bb = P.b[br];
    const float* row = xr + (size_t)wid * C_;
    __half* orow = xrh + (size_t)wid * C_;
    float s1 = 0.f, s2 = 0.f;
#pragma unroll
    for (int j = lane; j < C_; j += 32) {
        float v = row[j];
        s1 += v;
        s2 += v * v;
    }
#pragma unroll
    for (int o = 16; o; o >>= 1) {
        s1 += __shfl_xor_sync(0xffffffffu, s1, o);
        s2 += __shfl_xor_sync(0xffffffffu, s2, o);
    }
    float mu = s1 * (1.f / C_);
    float var = s2 * (1.f / C_) - mu * mu;
    float inv = rsqrtf(var + 1e-5f);
#pragma unroll
    for (int j = lane; j < C_; j += 32) {
        float v = (row[j] - mu) * inv * g[j] + bb[j];
        orow[j] = __float2half_rn(0.5f * v * (1.f + erff(v * 0.70710678118654752440f)));
    }
}

// =====================================================================================
// Batched depthwise 3x3 + residual; writes TRANSPOSED v2t[d][row].
// =====================================================================================
__global__ void dwconv_all_kernel(const float* __restrict__ kv, float* __restrict__ v2t,
                                  DwP P, int total)
{
    int idx = blockIdx.x * blockDim.x + threadIdx.x;
    if (idx >= total) return;
    int br = (idx >= P.e1) ? ((idx >= P.e2) ? 2 : 1) : 0;
    int local = idx - ((br == 0) ? 0 : (br == 1) ? P.e1 : P.e2);
    int s = P.s[br];
    int n = s * s;
    const float* w = P.w[br];
    const float* bias = P.c[br];
    int hd = local & 63;
    int p = (local >> 6) % n;
    int b = (local >> 6) / n;
    int y = p / s;
    int x0 = p - y * s;
    size_t base = (size_t)(P.o[br] + b * n);
    const float* vb = kv + base * 128 + 64 + hd;
    float acc = bias[hd];
#pragma unroll
    for (int dy = -1; dy <= 1; dy++) {
#pragma unroll
        for (int dx = -1; dx <= 1; dx++) {
            int yy = y + dy, xx = x0 + dx;
            if (yy >= 0 && yy < s && xx >= 0 && xx < s)
                acc += w[hd * 9 + (dy + 1) * 3 + (dx + 1)] * vb[(size_t)(yy * s + xx) * 128];
        }
    }
    v2t[(size_t)hd * RTOT_ + base + p] = acc + vb[(size_t)p * 128];
}

// =====================================================================================
// Batched flash attention, FULL FP16 MMA (m16n8k16), fp32 softmax/accum.
// Static smem: qs/kst [row|key][72 halves d-major], vs [d][72 halves key-major],
// ps [row][72 halves key-major]. All stride 36 words -> conflict-free frags.
// =====================================================================================
__global__ __launch_bounds__(128) void attn_all_kernel(
    const float* __restrict__ q, const float* __restrict__ kv,
    const float* __restrict__ v2t, __half* __restrict__ xcath, AtP P)
{
    __shared__ uint32_t qsw[64 * 36];
    __shared__ uint32_t kstw[64 * 36];
    __shared__ uint32_t vsw[64 * 36];
    __shared__ uint32_t psw[64 * 36];

    const int tid = threadIdx.x;
    const int warp = tid >> 5, lane = tid & 31;
    const int wm = warp;
    const int lr = lane >> 2, lc = lane & 3;
    const int b = blockIdx.y;
    const int head = blockIdx.z;
    const int q0 = blockIdx.x * 64;
    const int rr = wm * 16 + lr;
    const int nkv = P.nkv[head];
    const float* kvb = kv + (size_t)P.o[head] * 128;
    const float scale = 0.07216878364870322056f;  // 1/sqrt(192)

    // Q tile: rows q0..q0+63, 32 words of packed d
#pragma unroll
    for (int i = 0; i < 16; i++) {
        int e = tid + i * 128;
        int r = e >> 5, w = e & 31;
        const float* qp = q + ((size_t)b * N_ + q0 + r) * C_ + head * HD_ + 2 * w;
        float2 f = *(const float2*)qp;
        qsw[r * 36 + w] = packh2(f.x, f.y);
    }

    float m_i[2], l_i[2], oacc[8][4];
    m_i[0] = m_i[1] = -1e30f;
    l_i[0] = l_i[1] = 0.f;
#pragma unroll
    for (int ni = 0; ni < 8; ni++)
#pragma unroll
        for (int j = 0; j < 4; j++) oacc[ni][j] = 0.f;

    __syncthreads();

    const int nchunks = (nkv + 63) >> 6;
    for (int c0 = 0; c0 < nchunks; c0++) {
        int base = c0 * 64;
        int cs = nkv - base;
        if (cs > 64) cs = 64;
        // K: [key][d packed]
#pragma unroll
        for (int i = 0; i < 16; i++) {
            int e = tid + i * 128;
            int r = e >> 5, w = e & 31;
            uint32_t v = 0u;
            if (r < cs) {
                const float* kp = kvb + ((size_t)b * nkv + base + r) * 128 + 2 * w;
                float2 f = *(const float2*)kp;
                v = packh2(f.x, f.y);
            }
            kstw[r * 36 + w] = v;
        }
        // V: [d][key packed] from transposed v2t (scalar loads: parity of base varies)
        {
            const float* v2d = v2t + (size_t)P.o[head] + (size_t)b * nkv + base;
#pragma unroll
            for (int i = 0; i < 16; i++) {
                int e = tid + i * 128;
                int d = e >> 5, w = e & 31;
                int k0 = 2 * w, k1 = 2 * w + 1;
                const float* vp = v2d + (size_t)d * RTOT_;
                float f0 = (k0 < cs) ? vp[k0] : 0.f;
                float f1 = (k1 < cs) ? vp[k1] : 0.f;
                vsw[d * 36 + w] = packh2(f0, f1);
            }
        }
        __syncthreads();

        // S = Q @ K^T : 4 k16-steps
        float sacc[8][4];
#pragma unroll
        for (int ni = 0; ni < 8; ni++)
#pragma unroll
            for (int j = 0; j < 4; j++) sacc[ni][j] = 0.f;
#pragma unroll
        for (int ks = 0; ks < 4; ks++) {
            int ksw = ks * 8;
            uint32_t af[4];
            af[0] = qsw[rr * 36 + ksw + lc];
            af[1] = qsw[(rr + 8) * 36 + ksw + lc];
            af[2] = qsw[rr * 36 + ksw + 4 + lc];
            af[3] = qsw[(rr + 8) * 36 + ksw + 4 + lc];
#pragma unroll
            for (int ni = 0; ni < 8; ni++) {
                int cc = ni * 8 + lr;
                uint32_t bf[2];
                bf[0] = kstw[cc * 36 + ksw + lc];
                bf[1] = kstw[cc * 36 + ksw + 4 + lc];
                mma_f16(sacc[ni], af, bf);
            }
        }

        // online softmax (rows rr and rr+8)
#pragma unroll
        for (int h = 0; h < 2; h++) {
            float mx = -1e30f;
#pragma unroll
            for (int ni = 0; ni < 8; ni++)
#pragma unroll
                for (int j = 0; j < 2; j++) {
                    float v = sacc[ni][2 * h + j] * scale;
                    if (ni * 8 + 2 * lc + j >= cs) v = -1e30f;
                    sacc[ni][2 * h + j] = v;
                    mx = fmaxf(mx, v);
                }
            mx = fmaxf(mx, __shfl_xor_sync(0xffffffffu, mx, 1));
            mx = fmaxf(mx, __shfl_xor_sync(0xffffffffu, mx, 2));
            float mnew = fmaxf(m_i[h], mx);
            float alpha = __expf(m_i[h] - mnew);
            float rs = 0.f;
#pragma unroll
            for (int ni = 0; ni < 8; ni++)
#pragma unroll
                for (int j = 0; j < 2; j++) {
                    float p = __expf(sacc[ni][2 * h + j] - mnew);
                    sacc[ni][2 * h + j] = p;
                    rs += p;
                }
            rs += __shfl_xor_sync(0xffffffffu, rs, 1);
            rs += __shfl_xor_sync(0xffffffffu, rs, 2);
            l_i[h] = l_i[h] * alpha + rs;
            m_i[h] = mnew;
#pragma unroll
            for (int ni = 0; ni < 8; ni++) {
                oacc[ni][2 * h]     *= alpha;
                oacc[ni][2 * h + 1] *= alpha;
            }
        }

        // P -> smem as packed half2 (A operand of P@V); warp-private rows
#pragma unroll
        for (int ni = 0; ni < 8; ni++) {
            int wdx = ni * 4 + lc;
            psw[rr * 36 + wdx]       = packh2(sacc[ni][0], sacc[ni][1]);
            psw[(rr + 8) * 36 + wdx] = packh2(sacc[ni][2], sacc[ni][3]);
        }
        __syncwarp();

        // O += P @ V : 4 k16-steps over keys
#pragma unroll
        for (int ks = 0; ks < 4; ks++) {
            int ksw = ks * 8;
            uint32_t af[4];
            af[0] = psw[rr * 36 + ksw + lc];
            af[1] = psw[(rr + 8) * 36 + ksw + lc];
            af[2] = psw[rr * 36 + ksw + 4 + lc];
            af[3] = psw[(rr + 8) * 36 + ksw + 4 + lc];
#pragma unroll
            for (int ni = 0; ni < 8; ni++) {
                int cc = ni * 8 + lr;
                uint32_t bf[2];
                bf[0] = vsw[cc * 36 + ksw + lc];
                bf[1] = vsw[cc * 36 + ksw + 4 + lc];
                mma_f16(oacc[ni], af, bf);
            }
        }
        __syncthreads();
    }

    float inv0 = 1.f / l_i[0], inv1 = 1.f / l_i[1];
#pragma unroll
    for (int ni = 0; ni < 8; ni++) {
        int col = head * HD_ + ni * 8 + 2 * lc;
        size_t r0 = (size_t)b * N_ + q0 + rr;
        *(__half2*)(xcath + r0 * C_ + col) =
            __floats2half2_rn(oacc[ni][0] * inv0, oacc[ni][1] * inv0);
        *(__half2*)(xcath + (r0 + 8) * C_ + col) =
            __floats2half2_rn(oacc[ni][2] * inv1, oacc[ni][3] * inv1);
    }
}

// =====================================================================================
// Host orchestration: conv_all at profiled launch index 3.
// =====================================================================================
extern "C" void kernel_launch(void* const* d_in, const int* in_sizes, int n_in,
                              void* d_out, int out_size)
{
    const float* x   = (const float*)d_in[0];
    const float* Wq  = (const float*)d_in[1];
    const float* bq  = (const float*)d_in[2];
    const float* Wkv = (const float*)d_in[3];
    const float* bkv = (const float*)d_in[4];
    const float* Wo  = (const float*)d_in[23];
    const float* bo  = (const float*)d_in[24];

    float *q, *xr, *kvb, *v2t;
    __half *xh, *xrh, *xcath, *wth, *wqh, *wkvh, *woh;
    cudaGetSymbolAddress((void**)&q, g_q);
    cudaGetSymbolAddress((void**)&xr, g_xr);
    cudaGetSymbolAddress((void**)&kvb, g_kv);
    cudaGetSymbolAddress((void**)&v2t, g_v2t);
    cudaGetSymbolAddress((void**)&xh, g_xh);
    cudaGetSymbolAddress((void**)&xrh, g_xrh);
    cudaGetSymbolAddress((void**)&xcath, g_xcath);
    cudaGetSymbolAddress((void**)&wth, g_wth);
    cudaGetSymbolAddress((void**)&wqh, g_wqh);
    cudaGetSymbolAddress((void**)&wkvh, g_wkvh);
    cudaGetSymbolAddress((void**)&woh, g_woh);

    cudaFuncSetAttribute(gemm_tc_kernel, cudaFuncAttributeMaxDynamicSharedMemorySize,
                         PIPE_BYTES);
    cudaFuncSetAttribute(conv_all_kernel, cudaFuncAttributeMaxDynamicSharedMemorySize,
                         CPIPE_BYTES);

    const int M = B_ * N_;
    const int NX = B_ * N_ * C_;
    const int CC = C_ * C_;

    const int sA = 41, sB = 45, sC = 47;
    const int nA = sA * sA, nB = sB * sB, nC = sC * sC;
    const int oA = 0, oB = B_ * nA, oC = B_ * (nA + nB);
    const int rows = RTOT_;

    ConvP cp;
    cp.mb1 = (nA + 127) / 128;
    cp.mb2 = cp.mb1 + (nB + 127) / 128;
    int nblk = cp.mb2 + (nC + 127) / 128;
    cp.s[0] = sA; cp.s[1] = sB; cp.s[2] = sC;
    cp.k[0] = 8;  cp.k[1] = 4;  cp.k[2] = 2;
    cp.w[0] = 0;  cp.w[1] = 64 * CC; cp.w[2] = 80 * CC;
    cp.o[0] = oA; cp.o[1] = oB; cp.o[2] = oC;
    cp.bias[0] = (const float*)d_in[6];
    cp.bias[1] = (const float*)d_in[12];
    cp.bias[2] = (const float*)d_in[18];

    LnP lp;
    lp.r1 = oB; lp.r2 = oC;
    lp.g[0] = (const float*)d_in[7];  lp.b[0] = (const float*)d_in[8];
    lp.g[1] = (const float*)d_in[13]; lp.b[1] = (const float*)d_in[14];
    lp.g[2] = (const float*)d_in[19]; lp.b[2] = (const float*)d_in[20];

    DwP dp;
    dp.e1 = oB * 64; dp.e2 = oC * 64;
    dp.s[0] = sA; dp.s[1] = sB; dp.s[2] = sC;
    dp.o[0] = oA; dp.o[1] = oB; dp.o[2] = oC;
    dp.w[0] = (const float*)d_in[9];  dp.c[0] = (const float*)d_in[10];
    dp.w[1] = (const float*)d_in[15]; dp.c[1] = (const float*)d_in[16];
    dp.w[2] = (const float*)d_in[21]; dp.c[2] = (const float*)d_in[22];

    AtP ap;
    ap.nkv[0] = nA; ap.nkv[1] = nB; ap.nkv[2] = nC;
    ap.o[0] = oA; ap.o[1] = oB; ap.o[2] = oC;

    // 0
    cvt_x_kernel<<<(NX + 255) / 256, 256>>>(x, xh, NX);
    // 1
    cvt_w_kernel<<<(3 * CC + 255) / 256, 256>>>(Wq, Wkv, Wo, wqh, wkvh, woh);
    // 2
    wtrans_all_kernel<<<512, 256>>>((const float*)d_in[5], (const float*)d_in[11],
                                    (const float*)d_in[17], wth);
    // 3 (PROFILED): all SR convs
    conv_all_kernel<<<dim3(nblk, 3, B_), 128, CPIPE_BYTES>>>(xh, wth, xr, cp);
    // 4
    gemm_tc_kernel<<<dim3((M + 127) / 128, 3), 256, PIPE_BYTES>>>(
        xh, wqh, bq, q, M, C_, C_);
    // 5
    ln_gelu_all_kernel<<<(rows + 7) / 8, 256>>>(xr, xrh, lp, rows);
    // 6
    gemm_tc_kernel<<<dim3((rows + 127) / 128, 2), 256, PIPE_BYTES>>>(
        xrh, wkvh, bkv, kvb, rows, C_, 128);
    // 7
    dwconv_all_kernel<<<(rows * 64 + 255) / 256, 256>>>(kvb, v2t, dp, rows * 64);
    // 8
    attn_all_kernel<<<dim3(N_ / 64, B_, 3), 128>>>(q, kvb, v2t, xcath, ap);
    // 9
    gemm_tc_kernel<<<dim3((M + 127) / 128, 3), 256, PIPE_BYTES>>>(
        xcath, woh, bo, (float*)d_out, M, C_, C_);
}